// round 2
// baseline (speedup 1.0000x reference)
#include <cuda_runtime.h>
#include <cstdint>

// Problem constants (fixed by the reference setup_inputs)
#define NSCENE 16
#define VV     64
#define TT     32
#define CC     128
#define MT     32
#define MV     64
#define QT     2048      // V*T queries per scene
#define KT     2048      // mV*mT keys per scene
#define OUT_ELEMS (TT * NSCENE * VV * CC)   // 4194304
#define ATT_ELEMS (NSCENE * VV * MV)        // 65536

// Scratch: projected Q/K/V. K,V stored mt-major: row = n*KT + mt*MV + mv.
__device__ float g_Q[NSCENE * QT * CC];
__device__ float g_K[NSCENE * KT * CC];
__device__ float g_V[NSCENE * KT * CC];

// ---------------- packed f32x2 helpers ----------------
__device__ __forceinline__ void fma2(uint64_t& acc, uint64_t a, uint64_t b) {
    asm("fma.rn.f32x2 %0, %1, %2, %0;" : "+l"(acc) : "l"(a), "l"(b));
}
__device__ __forceinline__ uint64_t pack2(float x, float y) {
    uint64_t r;
    asm("mov.b64 %0, {%1, %2};" : "=l"(r) : "f"(x), "f"(y));
    return r;
}
__device__ __forceinline__ float2 unpack2(uint64_t v) {
    float2 f;
    asm("mov.b64 {%0, %1}, %2;" : "=f"(f.x), "=f"(f.y) : "l"(v));
    return f;
}

// ======================================================================
// Phase 1: projections. out = in @ W^T + b, with gather of the permuted
// source rows. Tile: 128 rows x 64 out-channels. grid = (256, 2, 3).
// ======================================================================
__global__ __launch_bounds__(256, 1) void proj_kernel(
    const float* __restrict__ P, const float* __restrict__ M,
    const float* __restrict__ Wq, const float* __restrict__ bq,
    const float* __restrict__ Wk, const float* __restrict__ bk,
    const float* __restrict__ Wv, const float* __restrict__ bv)
{
    extern __shared__ float sm[];
    float* As = sm;               // 128 * 132
    float* Ws = As + 128 * 132;   // 64 * 132
    float* bs = Ws + 64 * 132;    // 64

    const int rt = blockIdx.x;    // row tile (0..255)
    const int ch = blockIdx.y;    // out-channel half (0..1)
    const int sel = blockIdx.z;   // 0=Q, 1=K, 2=V

    const float* src; const float* W; const float* b; float* dst;
    if (sel == 0)      { src = P; W = Wq; b = bq; dst = g_Q; }
    else if (sel == 1) { src = M; W = Wk; b = bk; dst = g_K; }
    else               { src = M; W = Wv; b = bv; dst = g_V; }

    const int tid = threadIdx.x;

    // Load A rows (gathered) : 128 rows x 32 float4
    #pragma unroll
    for (int l = 0; l < 16; ++l) {
        int fi = tid + 256 * l;
        int r = fi >> 5, c4 = fi & 31;
        int rg = rt * 128 + r;
        int n = rg >> 11, rem = rg & 2047;
        int srcRow;
        if (sel == 0) { int v = rem >> 5, t = rem & 31; srcRow = (t << 10) + (n << 6) + v; }
        else          { int mt = rem >> 6, mv = rem & 63; srcRow = (mt << 10) + (n << 6) + mv; }
        *(float4*)&As[r * 132 + c4 * 4] = *(const float4*)&src[srcRow * CC + c4 * 4];
    }
    // Load W half: 64 rows x 32 float4
    #pragma unroll
    for (int l = 0; l < 8; ++l) {
        int fi = tid + 256 * l;
        int r = fi >> 5, c4 = fi & 31;
        *(float4*)&Ws[r * 132 + c4 * 4] = *(const float4*)&W[(ch * 64 + r) * CC + c4 * 4];
    }
    if (tid < 64) bs[tid] = b[ch * 64 + tid];
    __syncthreads();

    const int tx = tid & 15, ty = tid >> 4;
    uint64_t acc[8][4];
    #pragma unroll
    for (int i = 0; i < 8; ++i)
        #pragma unroll
        for (int j = 0; j < 4; ++j) acc[i][j] = 0ull;

    #pragma unroll 4
    for (int c4 = 0; c4 < 32; ++c4) {
        ulonglong2 av[8], wv[4];
        #pragma unroll
        for (int i = 0; i < 8; ++i)
            av[i] = *(const ulonglong2*)&As[(ty + 16 * i) * 132 + c4 * 4];
        #pragma unroll
        for (int j = 0; j < 4; ++j)
            wv[j] = *(const ulonglong2*)&Ws[(tx + 16 * j) * 132 + c4 * 4];
        #pragma unroll
        for (int i = 0; i < 8; ++i)
            #pragma unroll
            for (int j = 0; j < 4; ++j) {
                fma2(acc[i][j], av[i].x, wv[j].x);
                fma2(acc[i][j], av[i].y, wv[j].y);
            }
    }

    #pragma unroll
    for (int i = 0; i < 8; ++i) {
        int rg = rt * 128 + ty + 16 * i;
        #pragma unroll
        for (int j = 0; j < 4; ++j) {
            int cl = tx + 16 * j;
            float2 u = unpack2(acc[i][j]);
            dst[rg * CC + ch * 64 + cl] = u.x + u.y + bs[cl];
        }
    }
}

// ======================================================================
// Phase 2: fused attention. One block = (scene n, 128-query tile).
// Loop over the 32 mt groups; per group: S = Q Kg^T (128x64) + mask bias,
// exact softmax over mv (one thread per query, conflict-free at stride 65),
// O += A Vg, att accumulation.
// ======================================================================
#define SS_STRIDE 65

__global__ __launch_bounds__(256, 1) void attn_kernel(
    const void* __restrict__ maskp, float* __restrict__ dout, int write_att)
{
    extern __shared__ float sm[];
    float* Qs    = sm;             // 128*132 = 16896
    float* Ks    = Qs + 16896;     // 64*132  = 8448
    float* Vs    = Ks + 8448;      // 64*132  = 8448
    float* Ss    = Vs + 8448;      // 128*65  = 8320
    float* biasf = Ss + 8320;      // 64  (0 if valid, -1e9 if masked)
    __shared__ int s_okI, s_okF;

    const int tid = threadIdx.x;
    const int n = blockIdx.y, qt = blockIdx.x;
    const int q0 = qt * 128;

    // --- mask dtype classification (reads only first 1024 bytes: safe for all dtypes)
    if (tid == 0) { s_okI = 1; s_okF = 1; }
    __syncthreads();
    {
        unsigned x = ((const unsigned*)maskp)[tid];   // tid < 256 -> within 1024B
        if (!(x == 0u || x == 1u))          atomicAnd(&s_okI, 0);
        if (!(x == 0u || x == 0x3F800000u)) atomicAnd(&s_okF, 0);
    }

    // --- load Q tile (resident for all 32 iterations)
    #pragma unroll
    for (int l = 0; l < 16; ++l) {
        int fi = tid + 256 * l;
        int r = fi >> 5, c4 = fi & 31;
        *(float4*)&Qs[r * 132 + c4 * 4] =
            *(const float4*)&g_Q[(n * QT + q0 + r) * CC + c4 * 4];
    }
    __syncthreads();

    if (tid < 64) {
        int idx = n * 64 + tid;
        float mval;
        if (s_okI)      mval = (((const int*)maskp)[idx] != 0) ? 1.f : 0.f;
        else if (s_okF) mval = (((const float*)maskp)[idx] != 0.f) ? 1.f : 0.f;
        else            mval = (((const unsigned char*)maskp)[idx] != 0) ? 1.f : 0.f;
        biasf[tid] = (mval != 0.f) ? 0.f : -1e9f;
    }

    const int tx = tid & 15, ty = tid >> 4;
    uint64_t Oacc[8][4];     // output pairs: row ty+16i, cols (2*(tx+16j), +1)
    #pragma unroll
    for (int i = 0; i < 8; ++i)
        #pragma unroll
        for (int j = 0; j < 4; ++j) Oacc[i][j] = 0ull;
    float attReg = 0.f;
    const int a_vl = tid >> 6, a_mv = tid & 63;

    for (int mt = 0; mt < MT; ++mt) {
        // load K,V group tiles (64 x 128 each)
        const float* gk = &g_K[(n * KT + mt * MV) * CC];
        const float* gv = &g_V[(n * KT + mt * MV) * CC];
        #pragma unroll
        for (int l = 0; l < 8; ++l) {
            int fi = tid + 256 * l;
            int r = fi >> 5, c4 = fi & 31;
            *(float4*)&Ks[r * 132 + c4 * 4] = *(const float4*)&gk[r * CC + c4 * 4];
            *(float4*)&Vs[r * 132 + c4 * 4] = *(const float4*)&gv[r * CC + c4 * 4];
        }
        __syncthreads();

        // --- S = Q Kg^T, f32x2 pairing along the reduction dim
        uint64_t acc[8][4];
        #pragma unroll
        for (int i = 0; i < 8; ++i)
            #pragma unroll
            for (int j = 0; j < 4; ++j) acc[i][j] = 0ull;

        #pragma unroll 4
        for (int c4 = 0; c4 < 32; ++c4) {
            ulonglong2 qv[8], kv[4];
            #pragma unroll
            for (int i = 0; i < 8; ++i)
                qv[i] = *(const ulonglong2*)&Qs[(ty + 16 * i) * 132 + c4 * 4];
            #pragma unroll
            for (int j = 0; j < 4; ++j)
                kv[j] = *(const ulonglong2*)&Ks[(tx + 16 * j) * 132 + c4 * 4];
            #pragma unroll
            for (int i = 0; i < 8; ++i)
                #pragma unroll
                for (int j = 0; j < 4; ++j) {
                    fma2(acc[i][j], qv[i].x, kv[j].x);
                    fma2(acc[i][j], qv[i].y, kv[j].y);
                }
        }
        // Epilogue folds the mask in as an additive bias: exp() of a masked
        // entry underflows to exactly 0, reproducing both the masked softmax
        // and the post-softmax zeroing.
        #pragma unroll
        for (int i = 0; i < 8; ++i)
            #pragma unroll
            for (int j = 0; j < 4; ++j) {
                float2 u = unpack2(acc[i][j]);
                Ss[(ty + 16 * i) * SS_STRIDE + tx + 16 * j] =
                    u.x + u.y + biasf[tx + 16 * j];
            }
        __syncthreads();

        // --- exact softmax over the 64-wide group: one thread per query,
        //     stride-65 rows -> conflict-free LDS/STS
        if (tid < 128) {
            float* row = &Ss[tid * SS_STRIDE];
            float m = -1e30f;
            #pragma unroll 16
            for (int k = 0; k < MV; ++k) m = fmaxf(m, row[k]);
            float l = 0.f;
            #pragma unroll 16
            for (int k = 0; k < MV; ++k) {
                float e = __expf(row[k] - m);
                row[k] = e;
                l += e;
            }
            float inv = 1.f / l;
            #pragma unroll 16
            for (int k = 0; k < MV; ++k) row[k] *= inv;
        }
        __syncthreads();

        // --- att accumulation: one thread per (v_local, mv)
        {
            float s = 0.f;
            #pragma unroll
            for (int t = 0; t < TT; ++t) s += Ss[(a_vl * TT + t) * SS_STRIDE + a_mv];
            attReg += s;
        }

        // --- O += A Vg, f32x2 pairing along output columns
        #pragma unroll 2
        for (int k = 0; k < MV; ++k) {
            uint64_t a2[8];
            #pragma unroll
            for (int i = 0; i < 8; ++i) {
                float a = Ss[(ty + 16 * i) * SS_STRIDE + k];
                a2[i] = pack2(a, a);
            }
            uint64_t v2[4];
            #pragma unroll
            for (int j = 0; j < 4; ++j)
                v2[j] = *(const uint64_t*)&Vs[k * 132 + 2 * (tx + 16 * j)];
            #pragma unroll
            for (int i = 0; i < 8; ++i)
                #pragma unroll
                for (int j = 0; j < 4; ++j)
                    fma2(Oacc[i][j], a2[i], v2[j]);
        }
        __syncthreads();
    }

    // --- write O: out[t, n*V+v, c]
    #pragma unroll
    for (int i = 0; i < 8; ++i) {
        int q = q0 + ty + 16 * i;
        int t = q & 31, v = q >> 5;
        float* base = dout + ((size_t)((t << 10) + (n << 6) + v)) * CC;
        #pragma unroll
        for (int j = 0; j < 4; ++j) {
            int cp = tx + 16 * j;
            float2 u = unpack2(Oacc[i][j]);
            *(float2*)&base[2 * cp] = u;
        }
    }
    // --- write att: att[n, v, mv], mean over T*mT = 1024
    if (write_att) {
        dout[OUT_ELEMS + ((n * 64) + (qt * 4 + a_vl)) * 64 + a_mv] =
            attReg * (1.0f / 1024.0f);
    }
}

// ======================================================================
extern "C" void kernel_launch(void* const* d_in, const int* in_sizes, int n_in,
                              void* d_out, int out_size) {
    const float* P  = (const float*)d_in[0];
    const float* M  = (const float*)d_in[1];
    const void*  mk = d_in[2];
    const float* Wq = (const float*)d_in[3];
    const float* bq = (const float*)d_in[4];
    const float* Wk = (const float*)d_in[5];
    const float* bk = (const float*)d_in[6];
    const float* Wv = (const float*)d_in[7];
    const float* bv = (const float*)d_in[8];
    float* out = (float*)d_out;

    const int smem1 = (128 * 132 + 64 * 132 + 64) * 4;                      // 101,632 B
    const int smem2 = (16896 + 8448 + 8448 + 128 * SS_STRIDE + 64) * 4;     // 168,960 B
    cudaFuncSetAttribute(proj_kernel, cudaFuncAttributeMaxDynamicSharedMemorySize, smem1);
    cudaFuncSetAttribute(attn_kernel, cudaFuncAttributeMaxDynamicSharedMemorySize, smem2);

    int write_att = (out_size >= OUT_ELEMS + ATT_ELEMS) ? 1 : 0;

    proj_kernel<<<dim3(256, 2, 3), 256, smem1>>>(P, M, Wq, bq, Wk, bk, Wv, bv);
    attn_kernel<<<dim3(16, 16), 256, smem2>>>(mk, out, write_att);
}